// round 16
// baseline (speedup 1.0000x reference)
#include <cuda_runtime.h>
#include <cuda_bf16.h>
#include <cuda_fp16.h>
#include <cstdint>

// Self_Attn: B=4, C=512, N=4096 (64x64), D=64
// Outputs (tuple order): out [B,C,64,64] fp32, attention [B,N,N] fp32.

namespace {
constexpr int B_ = 4;
constexpr int C_ = 512;
constexpr int N_ = 4096;
constexpr int D_ = 64;

constexpr int KC_O = 64;             // out-GEMM K elems per chunk (128B fp16 row)
constexpr int NCHUNK_O = N_ / KC_O;  // 64
constexpr int STAGE_P = 32768;       // proj stage: A 16K + B 16K
constexpr int STAGE_O = 24576;       // out stage: A 16K + V 8K
constexpr int EPI_P = 132;           // epilogue smem pitch (floats)
constexpr int DYN_OUT = 2 * STAGE_O; // 49152 (2-stage; epi 33.8K reuses)
constexpr int DYN_E = 128 * EPI_P * 4;  // 67584
constexpr int DYN_V = 128 * EPI_P * 4;  // 67584
constexpr int DYN_QK = 2 * STAGE_P;  // 65536
}

// Scratch (device globals; no runtime allocation allowed).
__device__ __nv_bfloat16 g_qhi[B_ * N_ * D_];           // [B][N][D]
__device__ __nv_bfloat16 g_qlo[B_ * N_ * D_];
__device__ __nv_bfloat16 g_khi[B_ * N_ * D_];
__device__ __nv_bfloat16 g_klo[B_ * N_ * D_];
__device__ __nv_bfloat16 g_xthi[(size_t)B_ * N_ * C_];  // x^T [B][N][C] k-contig
__device__ __nv_bfloat16 g_xtlo[(size_t)B_ * N_ * C_];
__device__ __nv_bfloat16 g_wvhi[C_ * C_];               // Wv [c][k]
__device__ __nv_bfloat16 g_wvlo[C_ * C_];
__device__ __nv_bfloat16 g_wqkhi[128 * C_];             // stacked [Wq;Wk] [d][c]
__device__ __nv_bfloat16 g_wqklo[128 * C_];
__device__ __half g_vf16[(size_t)B_ * C_ * N_];         // v [B][C][N] fp16
__device__ __half g_af16[(size_t)B_ * N_ * N_];         // attn fp16 [B][M][N]

// ---------------------------------------------------------------------------
// helpers
// ---------------------------------------------------------------------------
__device__ __forceinline__ uint32_t smem_u32(const void* p) {
    uint32_t a;
    asm("{ .reg .u64 t; cvta.to.shared.u64 t, %1; cvt.u32.u64 %0, t; }" : "=r"(a) : "l"(p));
    return a;
}

__device__ __forceinline__ void cp16(uint32_t dst, const void* src) {
    asm volatile("cp.async.cg.shared.global [%0], [%1], 16;" :: "r"(dst), "l"(src) : "memory");
}

__device__ __forceinline__ void ldsm4(uint32_t* r, uint32_t addr) {
    asm volatile("ldmatrix.sync.aligned.m8n8.x4.shared.b16 {%0,%1,%2,%3}, [%4];"
                 : "=r"(r[0]), "=r"(r[1]), "=r"(r[2]), "=r"(r[3]) : "r"(addr));
}

__device__ __forceinline__ void mma_bf16(float* d, const uint32_t* a, uint32_t b0, uint32_t b1) {
    asm volatile(
        "mma.sync.aligned.m16n8k16.row.col.f32.bf16.bf16.f32 "
        "{%0,%1,%2,%3}, {%4,%5,%6,%7}, {%8,%9}, {%0,%1,%2,%3};"
        : "+f"(d[0]), "+f"(d[1]), "+f"(d[2]), "+f"(d[3])
        : "r"(a[0]), "r"(a[1]), "r"(a[2]), "r"(a[3]), "r"(b0), "r"(b1));
}

__device__ __forceinline__ void mma_f16(float* d, const uint32_t* a, uint32_t b0, uint32_t b1) {
    asm volatile(
        "mma.sync.aligned.m16n8k16.row.col.f32.f16.f16.f32 "
        "{%0,%1,%2,%3}, {%4,%5,%6,%7}, {%8,%9}, {%0,%1,%2,%3};"
        : "+f"(d[0]), "+f"(d[1]), "+f"(d[2]), "+f"(d[3])
        : "r"(a[0]), "r"(a[1]), "r"(a[2]), "r"(a[3]), "r"(b0), "r"(b1));
}

__device__ __forceinline__ uint32_t swz(uint32_t row, uint32_t colbyte) {
    return row * 128u + (colbyte ^ ((row & 7u) << 4));
}

__device__ __forceinline__ uint32_t pack_bf16(float a, float b) {
    __nv_bfloat162 h = __floats2bfloat162_rn(a, b);
    return *reinterpret_cast<uint32_t*>(&h);
}

// Streaming (evict-first) vector global accesses for single-use fp32 data.
__device__ __forceinline__ void st_cs_f4(float* p, float4 v) {
    asm volatile("st.global.cs.v4.f32 [%0], {%1,%2,%3,%4};"
                 :: "l"(p), "f"(v.x), "f"(v.y), "f"(v.z), "f"(v.w) : "memory");
}
__device__ __forceinline__ float4 ld_cs_f4(const float* p) {
    float4 v;
    asm volatile("ld.global.cs.v4.f32 {%0,%1,%2,%3}, [%4];"
                 : "=f"(v.x), "=f"(v.y), "=f"(v.z), "=f"(v.w) : "l"(p));
    return v;
}

// ---------------------------------------------------------------------------
// Transpose + split x: x[b][k][n] fp32 -> xT[b][n][k] bf16 hi/lo.
// ---------------------------------------------------------------------------
__global__ void convert_x_kernel(const float* __restrict__ x,
                                 __nv_bfloat16* __restrict__ xthi,
                                 __nv_bfloat16* __restrict__ xtlo) {
    const int b  = blockIdx.z;
    const int n0 = blockIdx.x * 32;
    const int k0 = blockIdx.y * 32;
    __shared__ float t[32][33];
    const int tid = threadIdx.x;
#pragma unroll
    for (int i = 0; i < 4; i++) {
        int idx = tid + i * 256;
        int k = idx >> 5, n = idx & 31;
        t[k][n] = x[((size_t)b * C_ + k0 + k) * N_ + n0 + n];
    }
    __syncthreads();
#pragma unroll
    for (int i = 0; i < 4; i++) {
        int idx = tid + i * 256;
        int n = idx >> 5, k = idx & 31;
        float val = t[k][n];
        __nv_bfloat16 h = __float2bfloat16(val);
        size_t off = ((size_t)b * N_ + n0 + n) * C_ + k0 + k;
        xthi[off] = h;
        xtlo[off] = __float2bfloat16(val - __bfloat162float(h));
    }
}

// Split Wv fp32 -> bf16 hi/lo.
__global__ void convert_w_kernel(const float* __restrict__ W,
                                 __nv_bfloat16* __restrict__ whi,
                                 __nv_bfloat16* __restrict__ wlo) {
    const int i = blockIdx.x * 256 + threadIdx.x;
    float val = W[i];
    __nv_bfloat16 h = __float2bfloat16(val);
    whi[i] = h;
    wlo[i] = __float2bfloat16(val - __bfloat162float(h));
}

// Stack Wq (rows 0..63) and Wk (rows 64..127) into Wqk bf16 hi/lo.
__global__ void convert_wqk_kernel(const float* __restrict__ Wq,
                                   const float* __restrict__ Wk,
                                   __nv_bfloat16* __restrict__ whi,
                                   __nv_bfloat16* __restrict__ wlo) {
    const int i = blockIdx.x * 256 + threadIdx.x;   // over 128*512
    const int d = i >> 9, c = i & 511;
    float val = d < 64 ? Wq[(size_t)d * C_ + c] : Wk[(size_t)(d - 64) * C_ + c];
    __nv_bfloat16 h = __float2bfloat16(val);
    whi[i] = h;
    wlo[i] = __float2bfloat16(val - __bfloat162float(h));
}

// ---------------------------------------------------------------------------
// proj_qk (HMMA, fused): CTA 128n x 128d, 2-stage ring, compensated bf16.
// ---------------------------------------------------------------------------
__global__ void __launch_bounds__(256, 2)
proj_qk_hmma_kernel(const float* __restrict__ bq, const float* __restrict__ bk,
                    __nv_bfloat16* __restrict__ qhi, __nv_bfloat16* __restrict__ qlo,
                    __nv_bfloat16* __restrict__ khi, __nv_bfloat16* __restrict__ klo) {
    extern __shared__ char dynsmem[];
    const uint32_t sbase = smem_u32(dynsmem);

    const int tid  = threadIdx.x;
    const int wid  = tid >> 5;
    const int lane = tid & 31;

    const int b  = blockIdx.z;
    const int n0 = blockIdx.x * 128;

    const __nv_bfloat16* Xhi = g_xthi + (size_t)b * N_ * C_;
    const __nv_bfloat16* Xlo = g_xtlo + (size_t)b * N_ * C_;

    const int wm = (wid >> 2) * 64;   // n
    const int wc = (wid & 3) * 32;    // d

    const uint32_t lrow = lane & 15;
    const uint32_t lswz = (lane & 7) << 4;
    const uint32_t lcol = (lane >> 4) << 4;

    float acc[4][4][4] = {};

    auto load_chunk = [&](int kc) {
        const uint32_t st = (uint32_t)(kc & 1) * STAGE_P;
        const size_t koff = (size_t)kc * 32;
#pragma unroll
        for (int t = 0; t < 8; t++) {
            const int idx = tid + t * 256;
            const int part = idx >> 10;          // 0=A(xT), 1=B(Wqk)
            const int a = idx & 1023;
            const int row = a >> 3, seg = a & 7;
            const __nv_bfloat16* src;
            if (part == 0)
                src = (seg < 4 ? Xhi : Xlo) + (size_t)(n0 + row) * C_ + koff + (seg & 3) * 8;
            else
                src = (seg < 4 ? g_wqkhi : g_wqklo) + (size_t)row * C_ + koff + (seg & 3) * 8;
            cp16(sbase + st + (uint32_t)part * 16384u + swz(row, seg * 16), src);
        }
        asm volatile("cp.async.commit_group;" ::: "memory");
    };

    load_chunk(0);

    for (int kc = 0; kc < C_ / 32; kc++) {
        asm volatile("cp.async.wait_group 0;" ::: "memory");
        __syncthreads();
        if (kc + 1 < C_ / 32) load_chunk(kc + 1);

        const uint32_t st = (uint32_t)(kc & 1) * STAGE_P;
        const uint32_t Ab = sbase + st, Bb = Ab + 16384;

#pragma unroll
        for (int ks = 0; ks < 2; ks++) {
            const uint32_t kbHi = (uint32_t)(ks * 32);
            const uint32_t kbLo = 64u + kbHi;

            uint32_t ah[4][4], al[4][4], bh[2][4], bl[2][4];
#pragma unroll
            for (int i = 0; i < 4; i++) {
                const uint32_t row = (uint32_t)(wm + i * 16) + lrow;
                ldsm4(ah[i], Ab + row * 128u + ((kbHi + lcol) ^ lswz));
                ldsm4(al[i], Ab + row * 128u + ((kbLo + lcol) ^ lswz));
            }
#pragma unroll
            for (int j = 0; j < 2; j++) {
                const uint32_t row = (uint32_t)(wc + j * 16) + lrow;
                ldsm4(bh[j], Bb + row * 128u + ((kbHi + lcol) ^ lswz));
                ldsm4(bl[j], Bb + row * 128u + ((kbLo + lcol) ^ lswz));
            }
#pragma unroll
            for (int i = 0; i < 4; i++)
#pragma unroll
                for (int j = 0; j < 4; j++) {
                    const int t2 = j >> 1, p2 = j & 1;
                    mma_bf16(acc[i][j], ah[i], bh[t2][p2], bh[t2][2 + p2]);
                    mma_bf16(acc[i][j], al[i], bh[t2][p2], bh[t2][2 + p2]);
                    mma_bf16(acc[i][j], ah[i], bl[t2][p2], bl[t2][2 + p2]);
                }
        }
        __syncthreads();
    }

    // Epilogue: bias add, split hi/lo, packed bf16x2 stores from registers.
#pragma unroll
    for (int j = 0; j < 4; j++) {
        const int d = wc + j * 8 + (lane & 3) * 2;   // even; pair never straddles 64
        const bool isq = d < 64;
        const int dd = isq ? d : d - 64;
        const float b0v = isq ? bq[dd] : bk[dd];
        const float b1v = isq ? bq[dd + 1] : bk[dd + 1];
        __nv_bfloat16* dhi = isq ? qhi : khi;
        __nv_bfloat16* dlo = isq ? qlo : klo;
#pragma unroll
        for (int i = 0; i < 4; i++) {
            const int n = n0 + wm + i * 16 + (lane >> 2);
#pragma unroll
            for (int r = 0; r < 2; r++) {          // row n, n+8
                const float v0 = acc[i][j][r * 2] + b0v;
                const float v1 = acc[i][j][r * 2 + 1] + b1v;
                const float h0 = __bfloat162float(__float2bfloat16(v0));
                const float h1 = __bfloat162float(__float2bfloat16(v1));
                const size_t off = ((size_t)b * N_ + n + r * 8) * D_ + dd;
                *reinterpret_cast<uint32_t*>(dhi + off) = pack_bf16(v0, v1);
                *reinterpret_cast<uint32_t*>(dlo + off) = pack_bf16(v0 - h0, v1 - h1);
            }
        }
    }
}

// ---------------------------------------------------------------------------
// proj_v (HMMA): v[b,c,n] = sum_k Wv[c,k] x[b,k,n] + bv[c], compensated bf16.
// ---------------------------------------------------------------------------
__global__ void __launch_bounds__(256, 2)
proj_v_hmma_kernel(const float* __restrict__ bias, __half* __restrict__ vf16) {
    extern __shared__ char dynsmem[];
    const uint32_t sbase = smem_u32(dynsmem);

    const int tid  = threadIdx.x;
    const int wid  = tid >> 5;
    const int lane = tid & 31;

    const int b  = blockIdx.z;
    const int c0 = blockIdx.x * 128;
    const int n0 = blockIdx.y * 128;

    const __nv_bfloat16* Whi = g_wvhi;
    const __nv_bfloat16* Wlo = g_wvlo;
    const __nv_bfloat16* Xhi = g_xthi + (size_t)b * N_ * C_;
    const __nv_bfloat16* Xlo = g_xtlo + (size_t)b * N_ * C_;

    const int wm = (wid >> 2) * 64;   // c
    const int wn = (wid & 3) * 32;    // n

    const uint32_t lrow = lane & 15;
    const uint32_t lswz = (lane & 7) << 4;
    const uint32_t lcol = (lane >> 4) << 4;

    float acc[4][4][4] = {};

    auto load_chunk = [&](int kc) {
        const uint32_t st = (uint32_t)(kc & 1) * STAGE_P;
        const size_t koff = (size_t)kc * 32;
#pragma unroll
        for (int t = 0; t < 8; t++) {
            const int idx = tid + t * 256;
            const int part = idx >> 10;          // 0=A(Wv), 1=B(xT)
            const int a = idx & 1023;
            const int row = a >> 3, seg = a & 7;
            const __nv_bfloat16* src;
            if (part == 0)
                src = (seg < 4 ? Whi : Wlo) + (size_t)(c0 + row) * C_ + koff + (seg & 3) * 8;
            else
                src = (seg < 4 ? Xhi : Xlo) + (size_t)(n0 + row) * C_ + koff + (seg & 3) * 8;
            cp16(sbase + st + (uint32_t)part * 16384u + swz(row, seg * 16), src);
        }
        asm volatile("cp.async.commit_group;" ::: "memory");
    };

    load_chunk(0);

    for (int kc = 0; kc < C_ / 32; kc++) {
        asm volatile("cp.async.wait_group 0;" ::: "memory");
        __syncthreads();
        if (kc + 1 < C_ / 32) load_chunk(kc + 1);

        const uint32_t st = (uint32_t)(kc & 1) * STAGE_P;
        const uint32_t Ab = sbase + st, Bb = Ab + 16384;

#pragma unroll
        for (int ks = 0; ks < 2; ks++) {
            const uint32_t kbHi = (uint32_t)(ks * 32);
            const uint32_t kbLo = 64u + kbHi;

            uint32_t ah[4][4], al[4][4], bh[2][4], bl[2][4];
#pragma unroll
            for (int i = 0; i < 4; i++) {
                const uint32_t row = (uint32_t)(wm + i * 16) + lrow;
                ldsm4(ah[i], Ab + row * 128u + ((kbHi + lcol) ^ lswz));
                ldsm4(al[i], Ab + row * 128u + ((kbLo + lcol) ^ lswz));
            }
#pragma unroll
            for (int j = 0; j < 2; j++) {
                const uint32_t row = (uint32_t)(wn + j * 16) + lrow;
                ldsm4(bh[j], Bb + row * 128u + ((kbHi + lcol) ^ lswz));
                ldsm4(bl[j], Bb + row * 128u + ((kbLo + lcol) ^ lswz));
            }
#pragma unroll
            for (int i = 0; i < 4; i++)
#pragma unroll
                for (int j = 0; j < 4; j++) {
                    const int t2 = j >> 1, p2 = j & 1;
                    mma_bf16(acc[i][j], ah[i], bh[t2][p2], bh[t2][2 + p2]);
                    mma_bf16(acc[i][j], al[i], bh[t2][p2], bh[t2][2 + p2]);
                    mma_bf16(acc[i][j], ah[i], bl[t2][p2], bl[t2][2 + p2]);
                }
        }
        __syncthreads();
    }

    // Epilogue: c-major rows in smem (n contiguous), add bias, emit fp16.
    float* sOut = reinterpret_cast<float*>(dynsmem);
#pragma unroll
    for (int i = 0; i < 4; i++) {
        const int ct = wm + i * 16 + (lane >> 2);
#pragma unroll
        for (int j = 0; j < 4; j++) {
            const int nt = wn + j * 8 + (lane & 3) * 2;
            sOut[ct * EPI_P + nt]           = acc[i][j][0];
            sOut[ct * EPI_P + nt + 1]       = acc[i][j][1];
            sOut[(ct + 8) * EPI_P + nt]     = acc[i][j][2];
            sOut[(ct + 8) * EPI_P + nt + 1] = acc[i][j][3];
        }
    }
    __syncthreads();

    const int row = tid >> 1;             // c within tile
    const int col0 = (tid & 1) * 64;      // n offset
    const float bv = bias[c0 + row];
    const float* srow = sOut + row * EPI_P + col0;
    __half* dst = vf16 + ((size_t)b * C_ + c0 + row) * N_ + n0 + col0;
#pragma unroll
    for (int v = 0; v < 16; v++) {
        float4 f = *reinterpret_cast<const float4*>(srow + v * 4);
        __half2 h01 = __floats2half2_rn(f.x + bv, f.y + bv);
        __half2 h23 = __floats2half2_rn(f.z + bv, f.w + bv);
        uint2 u;
        u.x = *reinterpret_cast<uint32_t*>(&h01);
        u.y = *reinterpret_cast<uint32_t*>(&h23);
        *reinterpret_cast<uint2*>(dst + v * 4) = u;
    }
}

// ---------------------------------------------------------------------------
// Energy (HMMA, single merged pass): per-batch instance.
// E written with .cs (evict-first): single-use streaming fp32.
// ---------------------------------------------------------------------------
__global__ void __launch_bounds__(256)
energy_hmma_kernel(float* __restrict__ attn, int b) {
    extern __shared__ char dynsmem[];
    const uint32_t sbase = smem_u32(dynsmem);

    const int tid  = threadIdx.x;
    const int wid  = tid >> 5;
    const int lane = tid & 31;

    const int n0 = blockIdx.x * 128;
    const int m0 = blockIdx.y * 128;

    const __nv_bfloat16* Qhi = g_qhi + (size_t)b * N_ * D_;
    const __nv_bfloat16* Qlo = g_qlo + (size_t)b * N_ * D_;
    const __nv_bfloat16* Khi = g_khi + (size_t)b * N_ * D_;
    const __nv_bfloat16* Klo = g_klo + (size_t)b * N_ * D_;

    const int wm = (wid >> 2) * 64;
    const int wn = (wid & 3) * 32;

    const uint32_t lrow = lane & 15;
    const uint32_t lswz = (lane & 7) << 4;
    const uint32_t lcol = (lane >> 4) << 4;

    // Load all four 16KB tiles: Qhi@0, Khi@16K, Qlo@32K, Klo@48K.
#pragma unroll
    for (int t = 0; t < 4; t++) {
        const int idx = tid + t * 256;
        const int row = idx >> 3, seg = idx & 7;
        cp16(sbase + swz(row, seg * 16), Qhi + (size_t)(m0 + row) * D_ + seg * 8);
        cp16(sbase + 16384 + swz(row, seg * 16), Khi + (size_t)(n0 + row) * D_ + seg * 8);
        cp16(sbase + 32768 + swz(row, seg * 16), Qlo + (size_t)(m0 + row) * D_ + seg * 8);
        cp16(sbase + 49152 + swz(row, seg * 16), Klo + (size_t)(n0 + row) * D_ + seg * 8);
    }
    asm volatile("cp.async.commit_group;" ::: "memory");

    float acc[4][4][4] = {};

    asm volatile("cp.async.wait_group 0;" ::: "memory");
    __syncthreads();

#pragma unroll
    for (int ks = 0; ks < 4; ks++) {
        const uint32_t kb = (uint32_t)(ks * 32);
        uint32_t ah[4][4], al[4][4], bh[2][4], bl[2][4];
#pragma unroll
        for (int i = 0; i < 4; i++) {
            const uint32_t row = (uint32_t)(wm + i * 16) + lrow;
            ldsm4(ah[i], sbase + row * 128u + ((kb + lcol) ^ lswz));
            ldsm4(al[i], sbase + 32768 + row * 128u + ((kb + lcol) ^ lswz));
        }
#pragma unroll
        for (int j = 0; j < 2; j++) {
            const uint32_t row = (uint32_t)(wn + j * 16) + lrow;
            ldsm4(bh[j], sbase + 16384 + row * 128u + ((kb + lcol) ^ lswz));
            ldsm4(bl[j], sbase + 49152 + row * 128u + ((kb + lcol) ^ lswz));
        }
#pragma unroll
        for (int i = 0; i < 4; i++)
#pragma unroll
            for (int j = 0; j < 4; j++) {
                const int t2 = j >> 1, p2 = j & 1;
                mma_bf16(acc[i][j], ah[i], bh[t2][p2], bh[t2][2 + p2]);
                mma_bf16(acc[i][j], al[i], bh[t2][p2], bh[t2][2 + p2]);
                mma_bf16(acc[i][j], ah[i], bl[t2][p2], bl[t2][2 + p2]);
            }
    }

    __syncthreads();
    float* sOut = reinterpret_cast<float*>(dynsmem);
#pragma unroll
    for (int i = 0; i < 4; i++) {
        const int mt = wm + i * 16 + (lane >> 2);
#pragma unroll
        for (int j = 0; j < 4; j++) {
            const int nt = wn + j * 8 + (lane & 3) * 2;
            sOut[mt * EPI_P + nt]           = acc[i][j][0];
            sOut[mt * EPI_P + nt + 1]       = acc[i][j][1];
            sOut[(mt + 8) * EPI_P + nt]     = acc[i][j][2];
            sOut[(mt + 8) * EPI_P + nt + 1] = acc[i][j][3];
        }
    }
    __syncthreads();

    float* eb = attn + (size_t)b * N_ * N_;
    const int row = tid >> 1;
    const int col0 = (tid & 1) * 64;
    const float* srow = sOut + row * EPI_P + col0;
    float* grow = eb + (size_t)(m0 + row) * N_ + n0 + col0;
#pragma unroll
    for (int v = 0; v < 16; v++)
        st_cs_f4(grow + v * 4, *reinterpret_cast<const float4*>(srow + v * 4));
}

// ---------------------------------------------------------------------------
// Row softmax in place (per-batch), no max subtraction (logits << 88).
// E read and attn fp32 store use .cs (single-use streaming); af16 default.
// ---------------------------------------------------------------------------
__global__ void softmax_kernel(float* __restrict__ attn,
                               __half* __restrict__ af16, int b) {
    const size_t row = (size_t)b * N_ + blockIdx.x;
    float* p = attn + row * N_;
    const int tid = threadIdx.x;

    float4 v[4];
    float s = 0.f;
#pragma unroll
    for (int i = 0; i < 4; i++) {
        v[i] = ld_cs_f4(p + tid * 4 + i * 1024);
        v[i].x = __expf(v[i].x); v[i].y = __expf(v[i].y);
        v[i].z = __expf(v[i].z); v[i].w = __expf(v[i].w);
        s += (v[i].x + v[i].y) + (v[i].z + v[i].w);
    }
    __shared__ float red[8];
#pragma unroll
    for (int o = 16; o; o >>= 1) s += __shfl_xor_sync(0xffffffffu, s, o);
    if ((tid & 31) == 0) red[tid >> 5] = s;
    __syncthreads();
    s = 0.f;
#pragma unroll
    for (int i = 0; i < 8; i++) s += red[i];
    const float inv = 1.0f / s;

    __half* ph = af16 + row * N_;
#pragma unroll
    for (int i = 0; i < 4; i++) {
        float4 r;
        r.x = v[i].x * inv; r.y = v[i].y * inv; r.z = v[i].z * inv; r.w = v[i].w * inv;
        st_cs_f4(p + tid * 4 + i * 1024, r);

        __half2 h01 = __floats2half2_rn(r.x, r.y);
        __half2 h23 = __floats2half2_rn(r.z, r.w);
        uint2 hh;
        hh.x = *reinterpret_cast<uint32_t*>(&h01);
        hh.y = *reinterpret_cast<uint32_t*>(&h23);
        *reinterpret_cast<uint2*>(ph + tid * 4 + i * 1024) = hh;
    }
}

// ---------------------------------------------------------------------------
// out-GEMM (per-batch): HMMA fp16, CTA 128m x 64c, 2-stage ring, 3 CTAs/SM.
// ---------------------------------------------------------------------------
__global__ void __launch_bounds__(256, 3)
out_gemm_kernel(const float* __restrict__ x,
                const float* __restrict__ gamma,
                float* __restrict__ out, int b) {
    extern __shared__ char dynsmem[];
    const uint32_t sbase = smem_u32(dynsmem);

    const int tid  = threadIdx.x;
    const int wid  = tid >> 5;
    const int lane = tid & 31;

    const int c0 = blockIdx.x * 64;    // c fastest: 8 siblings share A tile in L2
    const int m0 = blockIdx.y * 128;

    const __half* A = g_af16 + (size_t)b * N_ * N_;
    const __half* V = g_vf16 + (size_t)b * C_ * N_;

    const int wm = (wid >> 2) * 64;    // m offset of warp
    const int wc = (wid & 3) * 16;     // c offset of warp

    const uint32_t lrow = lane & 15;
    const uint32_t lswz = (lane & 7) << 4;
    const uint32_t lcol = (lane >> 4) << 4;

    float acc[4][2][4] = {};   // [m16][c8][reg]

    auto load_chunk = [&](int kc) {
        const uint32_t st = (uint32_t)(kc & 1) * STAGE_O;
        const size_t koff = (size_t)kc * KC_O;
#pragma unroll
        for (int t = 0; t < 6; t++) {
            const int idx = tid + t * 256;
            if (idx < 1024) {
                const int row = idx >> 3, seg = idx & 7;
                cp16(sbase + st + swz(row, seg * 16),
                     A + (size_t)(m0 + row) * N_ + koff + seg * 8);
            } else {
                const int i2 = idx - 1024;
                const int row = i2 >> 3, seg = i2 & 7;
                cp16(sbase + st + 16384u + swz(row, seg * 16),
                     V + (size_t)(c0 + row) * N_ + koff + seg * 8);
            }
        }
        asm volatile("cp.async.commit_group;" ::: "memory");
    };

    load_chunk(0);

    for (int kc = 0; kc < NCHUNK_O; kc++) {
        asm volatile("cp.async.wait_group 0;" ::: "memory");
        __syncthreads();
        if (kc + 1 < NCHUNK_O) load_chunk(kc + 1);

        const uint32_t st = (uint32_t)(kc & 1) * STAGE_O;
        const uint32_t Ab = sbase + st, Vb = Ab + 16384;

#pragma unroll
        for (int ks = 0; ks < 4; ks++) {
            const uint32_t kb = (uint32_t)(ks * 32);
            uint32_t a[4][4], bm[4];
#pragma unroll
            for (int i = 0; i < 4; i++) {
                const uint32_t row = (uint32_t)(wm + i * 16) + lrow;
                ldsm4(a[i], Ab + row * 128u + ((kb + lcol) ^ lswz));
            }
            {
                const uint32_t row = (uint32_t)wc + lrow;
                ldsm4(bm, Vb + row * 128u + ((kb + lcol) ^ lswz));
            }
#pragma unroll
            for (int i = 0; i < 4; i++)
#pragma unroll
                for (int p2 = 0; p2 < 2; p2++)
                    mma_f16(acc[i][p2], a[i], bm[p2], bm[2 + p2]);
        }
    }
    __syncthreads();

    // ---- epilogue: full 64c x 128m transpose via smem ----
    float* sOut = reinterpret_cast<float*>(dynsmem);
#pragma unroll
    for (int i = 0; i < 4; i++) {
        const int mt = wm + i * 16 + (lane >> 2);
#pragma unroll
        for (int p2 = 0; p2 < 2; p2++) {
            const int ct = wc + p2 * 8 + (lane & 3) * 2;
            sOut[ct * EPI_P + mt]           = acc[i][p2][0];
            sOut[(ct + 1) * EPI_P + mt]     = acc[i][p2][1];
            sOut[ct * EPI_P + mt + 8]       = acc[i][p2][2];
            sOut[(ct + 1) * EPI_P + mt + 8] = acc[i][p2][3];
        }
    }
    __syncthreads();

    const float g = gamma[0];
    const int ce = tid >> 2;             // 0..63
    const int me = (tid & 3) * 32;       // m offset
    const size_t gb = ((size_t)b * C_ + c0 + ce) * N_ + m0 + me;
    const float* srow = sOut + ce * EPI_P + me;
#pragma unroll
    for (int v = 0; v < 8; v++) {
        const float4 xv = *reinterpret_cast<const float4*>(x + gb + v * 4);
        float4 ov;
        ov.x = g * srow[v * 4 + 0] + xv.x;
        ov.y = g * srow[v * 4 + 1] + xv.y;
        ov.z = g * srow[v * 4 + 2] + xv.z;
        ov.w = g * srow[v * 4 + 3] + xv.w;
        *reinterpret_cast<float4*>(out + gb + v * 4) = ov;
    }
}

// ---------------------------------------------------------------------------
extern "C" void kernel_launch(void* const* d_in, const int* in_sizes, int n_in,
                              void* d_out, int out_size) {
    (void)in_sizes; (void)n_in; (void)out_size;
    const float* x     = (const float*)d_in[0];
    const float* Wq    = (const float*)d_in[1];
    const float* bq    = (const float*)d_in[2];
    const float* Wk    = (const float*)d_in[3];
    const float* bk    = (const float*)d_in[4];
    const float* Wv    = (const float*)d_in[5];
    const float* bv    = (const float*)d_in[6];
    const float* gamma = (const float*)d_in[7];

    float* out  = (float*)d_out;
    float* attn = out + (size_t)B_ * C_ * N_;   // tuple order: (out, attention)

    __nv_bfloat16 *qhi, *qlo, *khi, *klo, *xthi, *xtlo, *wvhi, *wvlo, *wqkhi, *wqklo;
    __half *vf16, *af16;
    cudaGetSymbolAddress((void**)&qhi, g_qhi);
    cudaGetSymbolAddress((void**)&qlo, g_qlo);
    cudaGetSymbolAddress((void**)&khi, g_khi);
    cudaGetSymbolAddress((void**)&klo, g_klo);
    cudaGetSymbolAddress((void**)&xthi, g_xthi);
    cudaGetSymbolAddress((void**)&xtlo, g_xtlo);
    cudaGetSymbolAddress((void**)&wvhi, g_wvhi);
    cudaGetSymbolAddress((void**)&wvlo, g_wvlo);
    cudaGetSymbolAddress((void**)&wqkhi, g_wqkhi);
    cudaGetSymbolAddress((void**)&wqklo, g_wqklo);
    cudaGetSymbolAddress((void**)&vf16, g_vf16);
    cudaGetSymbolAddress((void**)&af16, g_af16);

    cudaFuncSetAttribute(out_gemm_kernel,
                         cudaFuncAttributeMaxDynamicSharedMemorySize, DYN_OUT);
    cudaFuncSetAttribute(energy_hmma_kernel,
                         cudaFuncAttributeMaxDynamicSharedMemorySize, DYN_E);
    cudaFuncSetAttribute(proj_v_hmma_kernel,
                         cudaFuncAttributeMaxDynamicSharedMemorySize, DYN_V);
    cudaFuncSetAttribute(proj_qk_hmma_kernel,
                         cudaFuncAttributeMaxDynamicSharedMemorySize, DYN_QK);

    // ONE extra stream + 6 events (proven-safe resource budget). R13 schedule.
    cudaStream_t s1;
    cudaStreamCreateWithFlags(&s1, cudaStreamNonBlocking);
    cudaEvent_t eFork, eX, eWqk, eV, eQK, eDone;
    cudaEventCreateWithFlags(&eFork, cudaEventDisableTiming);
    cudaEventCreateWithFlags(&eX,    cudaEventDisableTiming);
    cudaEventCreateWithFlags(&eWqk,  cudaEventDisableTiming);
    cudaEventCreateWithFlags(&eV,    cudaEventDisableTiming);
    cudaEventCreateWithFlags(&eQK,   cudaEventDisableTiming);
    cudaEventCreateWithFlags(&eDone, cudaEventDisableTiming);

    dim3 blk(256);

    // fork side stream off the (captured) legacy stream
    cudaEventRecord(eFork, 0);
    cudaStreamWaitEvent(s1, eFork, 0);

    // s1: weight converts (independent of x)
    convert_w_kernel<<<dim3(C_ * C_ / 256), blk, 0, s1>>>(Wv, wvhi, wvlo);
    convert_wqk_kernel<<<dim3(128 * C_ / 256), blk, 0, s1>>>(Wq, Wk, wqkhi, wqklo);
    cudaEventRecord(eWqk, s1);

    // s0: x transpose/split
    convert_x_kernel<<<dim3(N_ / 32, C_ / 32, B_), blk>>>(x, xthi, xtlo);
    cudaEventRecord(eX, 0);

    // s1: proj_v (needs convert_x + convert_w) — overlaps proj_qk/energy(b0)
    cudaStreamWaitEvent(s1, eX, 0);
    proj_v_hmma_kernel<<<dim3(C_ / 128, N_ / 128, B_), blk, DYN_V, s1>>>(bv, vf16);
    cudaEventRecord(eV, s1);

    // s0: proj_qk (needs convert_x + convert_wqk)
    cudaStreamWaitEvent(0, eWqk, 0);
    proj_qk_hmma_kernel<<<dim3(N_ / 128, 1, B_), blk, DYN_QK>>>(bq, bk, qhi, qlo, khi, klo);
    cudaEventRecord(eQK, 0);

    // Two-way batch pipeline: s0 handles b=0,2; s1 handles b=1,3.
    cudaStreamWaitEvent(s1, eQK, 0);
    for (int i = 0; i < 2; i++) {
        const int b0 = 2 * i;      // s0 batches: 0, 2
        const int b1 = 2 * i + 1;  // s1 batches: 1, 3

        energy_hmma_kernel<<<dim3(N_ / 128, N_ / 128, 1), blk, DYN_E, 0>>>(attn, b0);
        energy_hmma_kernel<<<dim3(N_ / 128, N_ / 128, 1), blk, DYN_E, s1>>>(attn, b1);

        softmax_kernel<<<dim3(N_), blk, 0, 0>>>(attn, af16, b0);
        softmax_kernel<<<dim3(N_), blk, 0, s1>>>(attn, af16, b1);

        if (i == 0) cudaStreamWaitEvent(0, eV, 0);   // v ready before first out_gemm
        out_gemm_kernel<<<dim3(C_ / 64, N_ / 128, 1), blk, DYN_OUT, 0>>>(x, gamma, out, b0);
        out_gemm_kernel<<<dim3(C_ / 64, N_ / 128, 1), blk, DYN_OUT, s1>>>(x, gamma, out, b1);
    }

    // join s1 back to the legacy (capture-origin) stream
    cudaEventRecord(eDone, s1);
    cudaStreamWaitEvent(0, eDone, 0);
}

// round 17
// speedup vs baseline: 1.0504x; 1.0504x over previous
#include <cuda_runtime.h>
#include <cuda_bf16.h>
#include <cuda_fp16.h>
#include <cstdint>

// Self_Attn: B=4, C=512, N=4096 (64x64), D=64
// Outputs (tuple order): out [B,C,64,64] fp32, attention [B,N,N] fp32.

namespace {
constexpr int B_ = 4;
constexpr int C_ = 512;
constexpr int N_ = 4096;
constexpr int D_ = 64;

constexpr int KC_O = 64;             // out-GEMM K elems per chunk (128B fp16 row)
constexpr int NCHUNK_O = N_ / KC_O;  // 64
constexpr int STAGE_P = 32768;       // proj stage: A 16K + B 16K
constexpr int STAGE_O = 24576;       // out stage: A 16K + V 8K
constexpr int EPI_P = 132;           // epilogue smem pitch (floats)
constexpr int DYN_OUT = 2 * STAGE_O; // 49152 (2-stage; epi 33.8K reuses)
constexpr int DYN_E = 128 * EPI_P * 4;  // 67584
constexpr int DYN_V = 128 * EPI_P * 4;  // 67584
constexpr int DYN_QK = 2 * STAGE_P;  // 65536
}

// Scratch (device globals; no runtime allocation allowed).
__device__ __nv_bfloat16 g_qhi[B_ * N_ * D_];           // [B][N][D]
__device__ __nv_bfloat16 g_qlo[B_ * N_ * D_];
__device__ __nv_bfloat16 g_khi[B_ * N_ * D_];
__device__ __nv_bfloat16 g_klo[B_ * N_ * D_];
__device__ __nv_bfloat16 g_xthi[(size_t)B_ * N_ * C_];  // x^T [B][N][C] k-contig
__device__ __nv_bfloat16 g_xtlo[(size_t)B_ * N_ * C_];
__device__ __nv_bfloat16 g_wvhi[C_ * C_];               // Wv [c][k]
__device__ __nv_bfloat16 g_wvlo[C_ * C_];
__device__ __nv_bfloat16 g_wqkhi[128 * C_];             // stacked [Wq;Wk] [d][c]
__device__ __nv_bfloat16 g_wqklo[128 * C_];
__device__ __half g_vf16[(size_t)B_ * C_ * N_];         // v [B][C][N] fp16
__device__ __half g_af16[(size_t)B_ * N_ * N_];         // attn fp16 [B][M][N]

// ---------------------------------------------------------------------------
// helpers
// ---------------------------------------------------------------------------
__device__ __forceinline__ uint32_t smem_u32(const void* p) {
    uint32_t a;
    asm("{ .reg .u64 t; cvta.to.shared.u64 t, %1; cvt.u32.u64 %0, t; }" : "=r"(a) : "l"(p));
    return a;
}

__device__ __forceinline__ void cp16(uint32_t dst, const void* src) {
    asm volatile("cp.async.cg.shared.global [%0], [%1], 16;" :: "r"(dst), "l"(src) : "memory");
}

__device__ __forceinline__ void ldsm4(uint32_t* r, uint32_t addr) {
    asm volatile("ldmatrix.sync.aligned.m8n8.x4.shared.b16 {%0,%1,%2,%3}, [%4];"
                 : "=r"(r[0]), "=r"(r[1]), "=r"(r[2]), "=r"(r[3]) : "r"(addr));
}

__device__ __forceinline__ void mma_bf16(float* d, const uint32_t* a, uint32_t b0, uint32_t b1) {
    asm volatile(
        "mma.sync.aligned.m16n8k16.row.col.f32.bf16.bf16.f32 "
        "{%0,%1,%2,%3}, {%4,%5,%6,%7}, {%8,%9}, {%0,%1,%2,%3};"
        : "+f"(d[0]), "+f"(d[1]), "+f"(d[2]), "+f"(d[3])
        : "r"(a[0]), "r"(a[1]), "r"(a[2]), "r"(a[3]), "r"(b0), "r"(b1));
}

__device__ __forceinline__ void mma_f16(float* d, const uint32_t* a, uint32_t b0, uint32_t b1) {
    asm volatile(
        "mma.sync.aligned.m16n8k16.row.col.f32.f16.f16.f32 "
        "{%0,%1,%2,%3}, {%4,%5,%6,%7}, {%8,%9}, {%0,%1,%2,%3};"
        : "+f"(d[0]), "+f"(d[1]), "+f"(d[2]), "+f"(d[3])
        : "r"(a[0]), "r"(a[1]), "r"(a[2]), "r"(a[3]), "r"(b0), "r"(b1));
}

__device__ __forceinline__ uint32_t swz(uint32_t row, uint32_t colbyte) {
    return row * 128u + (colbyte ^ ((row & 7u) << 4));
}

__device__ __forceinline__ uint32_t pack_bf16(float a, float b) {
    __nv_bfloat162 h = __floats2bfloat162_rn(a, b);
    return *reinterpret_cast<uint32_t*>(&h);
}

// Evict-first store: for data never read again on-device (attn fp32 output).
__device__ __forceinline__ void st_cs_f4(float* p, float4 v) {
    asm volatile("st.global.cs.v4.f32 [%0], {%1,%2,%3,%4};"
                 :: "l"(p), "f"(v.x), "f"(v.y), "f"(v.z), "f"(v.w) : "memory");
}

// ---------------------------------------------------------------------------
// Transpose + split x: x[b][k][n] fp32 -> xT[b][n][k] bf16 hi/lo.
// ---------------------------------------------------------------------------
__global__ void convert_x_kernel(const float* __restrict__ x,
                                 __nv_bfloat16* __restrict__ xthi,
                                 __nv_bfloat16* __restrict__ xtlo) {
    const int b  = blockIdx.z;
    const int n0 = blockIdx.x * 32;
    const int k0 = blockIdx.y * 32;
    __shared__ float t[32][33];
    const int tid = threadIdx.x;
#pragma unroll
    for (int i = 0; i < 4; i++) {
        int idx = tid + i * 256;
        int k = idx >> 5, n = idx & 31;
        t[k][n] = x[((size_t)b * C_ + k0 + k) * N_ + n0 + n];
    }
    __syncthreads();
#pragma unroll
    for (int i = 0; i < 4; i++) {
        int idx = tid + i * 256;
        int n = idx >> 5, k = idx & 31;
        float val = t[k][n];
        __nv_bfloat16 h = __float2bfloat16(val);
        size_t off = ((size_t)b * N_ + n0 + n) * C_ + k0 + k;
        xthi[off] = h;
        xtlo[off] = __float2bfloat16(val - __bfloat162float(h));
    }
}

// Split Wv fp32 -> bf16 hi/lo.
__global__ void convert_w_kernel(const float* __restrict__ W,
                                 __nv_bfloat16* __restrict__ whi,
                                 __nv_bfloat16* __restrict__ wlo) {
    const int i = blockIdx.x * 256 + threadIdx.x;
    float val = W[i];
    __nv_bfloat16 h = __float2bfloat16(val);
    whi[i] = h;
    wlo[i] = __float2bfloat16(val - __bfloat162float(h));
}

// Stack Wq (rows 0..63) and Wk (rows 64..127) into Wqk bf16 hi/lo.
__global__ void convert_wqk_kernel(const float* __restrict__ Wq,
                                   const float* __restrict__ Wk,
                                   __nv_bfloat16* __restrict__ whi,
                                   __nv_bfloat16* __restrict__ wlo) {
    const int i = blockIdx.x * 256 + threadIdx.x;   // over 128*512
    const int d = i >> 9, c = i & 511;
    float val = d < 64 ? Wq[(size_t)d * C_ + c] : Wk[(size_t)(d - 64) * C_ + c];
    __nv_bfloat16 h = __float2bfloat16(val);
    whi[i] = h;
    wlo[i] = __float2bfloat16(val - __bfloat162float(h));
}

// ---------------------------------------------------------------------------
// proj_qk (HMMA, fused): CTA 128n x 128d, 2-stage ring, compensated bf16.
// ---------------------------------------------------------------------------
__global__ void __launch_bounds__(256, 2)
proj_qk_hmma_kernel(const float* __restrict__ bq, const float* __restrict__ bk,
                    __nv_bfloat16* __restrict__ qhi, __nv_bfloat16* __restrict__ qlo,
                    __nv_bfloat16* __restrict__ khi, __nv_bfloat16* __restrict__ klo) {
    extern __shared__ char dynsmem[];
    const uint32_t sbase = smem_u32(dynsmem);

    const int tid  = threadIdx.x;
    const int wid  = tid >> 5;
    const int lane = tid & 31;

    const int b  = blockIdx.z;
    const int n0 = blockIdx.x * 128;

    const __nv_bfloat16* Xhi = g_xthi + (size_t)b * N_ * C_;
    const __nv_bfloat16* Xlo = g_xtlo + (size_t)b * N_ * C_;

    const int wm = (wid >> 2) * 64;   // n
    const int wc = (wid & 3) * 32;    // d

    const uint32_t lrow = lane & 15;
    const uint32_t lswz = (lane & 7) << 4;
    const uint32_t lcol = (lane >> 4) << 4;

    float acc[4][4][4] = {};

    auto load_chunk = [&](int kc) {
        const uint32_t st = (uint32_t)(kc & 1) * STAGE_P;
        const size_t koff = (size_t)kc * 32;
#pragma unroll
        for (int t = 0; t < 8; t++) {
            const int idx = tid + t * 256;
            const int part = idx >> 10;          // 0=A(xT), 1=B(Wqk)
            const int a = idx & 1023;
            const int row = a >> 3, seg = a & 7;
            const __nv_bfloat16* src;
            if (part == 0)
                src = (seg < 4 ? Xhi : Xlo) + (size_t)(n0 + row) * C_ + koff + (seg & 3) * 8;
            else
                src = (seg < 4 ? g_wqkhi : g_wqklo) + (size_t)row * C_ + koff + (seg & 3) * 8;
            cp16(sbase + st + (uint32_t)part * 16384u + swz(row, seg * 16), src);
        }
        asm volatile("cp.async.commit_group;" ::: "memory");
    };

    load_chunk(0);

    for (int kc = 0; kc < C_ / 32; kc++) {
        asm volatile("cp.async.wait_group 0;" ::: "memory");
        __syncthreads();
        if (kc + 1 < C_ / 32) load_chunk(kc + 1);

        const uint32_t st = (uint32_t)(kc & 1) * STAGE_P;
        const uint32_t Ab = sbase + st, Bb = Ab + 16384;

#pragma unroll
        for (int ks = 0; ks < 2; ks++) {
            const uint32_t kbHi = (uint32_t)(ks * 32);
            const uint32_t kbLo = 64u + kbHi;

            uint32_t ah[4][4], al[4][4], bh[2][4], bl[2][4];
#pragma unroll
            for (int i = 0; i < 4; i++) {
                const uint32_t row = (uint32_t)(wm + i * 16) + lrow;
                ldsm4(ah[i], Ab + row * 128u + ((kbHi + lcol) ^ lswz));
                ldsm4(al[i], Ab + row * 128u + ((kbLo + lcol) ^ lswz));
            }
#pragma unroll
            for (int j = 0; j < 2; j++) {
                const uint32_t row = (uint32_t)(wc + j * 16) + lrow;
                ldsm4(bh[j], Bb + row * 128u + ((kbHi + lcol) ^ lswz));
                ldsm4(bl[j], Bb + row * 128u + ((kbLo + lcol) ^ lswz));
            }
#pragma unroll
            for (int i = 0; i < 4; i++)
#pragma unroll
                for (int j = 0; j < 4; j++) {
                    const int t2 = j >> 1, p2 = j & 1;
                    mma_bf16(acc[i][j], ah[i], bh[t2][p2], bh[t2][2 + p2]);
                    mma_bf16(acc[i][j], al[i], bh[t2][p2], bh[t2][2 + p2]);
                    mma_bf16(acc[i][j], ah[i], bl[t2][p2], bl[t2][2 + p2]);
                }
        }
        __syncthreads();
    }

    // Epilogue: bias add, split hi/lo, packed bf16x2 stores from registers.
#pragma unroll
    for (int j = 0; j < 4; j++) {
        const int d = wc + j * 8 + (lane & 3) * 2;   // even; pair never straddles 64
        const bool isq = d < 64;
        const int dd = isq ? d : d - 64;
        const float b0v = isq ? bq[dd] : bk[dd];
        const float b1v = isq ? bq[dd + 1] : bk[dd + 1];
        __nv_bfloat16* dhi = isq ? qhi : khi;
        __nv_bfloat16* dlo = isq ? qlo : klo;
#pragma unroll
        for (int i = 0; i < 4; i++) {
            const int n = n0 + wm + i * 16 + (lane >> 2);
#pragma unroll
            for (int r = 0; r < 2; r++) {          // row n, n+8
                const float v0 = acc[i][j][r * 2] + b0v;
                const float v1 = acc[i][j][r * 2 + 1] + b1v;
                const float h0 = __bfloat162float(__float2bfloat16(v0));
                const float h1 = __bfloat162float(__float2bfloat16(v1));
                const size_t off = ((size_t)b * N_ + n + r * 8) * D_ + dd;
                *reinterpret_cast<uint32_t*>(dhi + off) = pack_bf16(v0, v1);
                *reinterpret_cast<uint32_t*>(dlo + off) = pack_bf16(v0 - h0, v1 - h1);
            }
        }
    }
}

// ---------------------------------------------------------------------------
// proj_v (HMMA): v[b,c,n] = sum_k Wv[c,k] x[b,k,n] + bv[c], compensated bf16.
// Monolithic over batches (grid.z = B) — best measured occupancy config.
// ---------------------------------------------------------------------------
__global__ void __launch_bounds__(256, 2)
proj_v_hmma_kernel(const float* __restrict__ bias, __half* __restrict__ vf16) {
    extern __shared__ char dynsmem[];
    const uint32_t sbase = smem_u32(dynsmem);

    const int tid  = threadIdx.x;
    const int wid  = tid >> 5;
    const int lane = tid & 31;

    const int b  = blockIdx.z;
    const int c0 = blockIdx.x * 128;
    const int n0 = blockIdx.y * 128;

    const __nv_bfloat16* Whi = g_wvhi;
    const __nv_bfloat16* Wlo = g_wvlo;
    const __nv_bfloat16* Xhi = g_xthi + (size_t)b * N_ * C_;
    const __nv_bfloat16* Xlo = g_xtlo + (size_t)b * N_ * C_;

    const int wm = (wid >> 2) * 64;   // c
    const int wn = (wid & 3) * 32;    // n

    const uint32_t lrow = lane & 15;
    const uint32_t lswz = (lane & 7) << 4;
    const uint32_t lcol = (lane >> 4) << 4;

    float acc[4][4][4] = {};

    auto load_chunk = [&](int kc) {
        const uint32_t st = (uint32_t)(kc & 1) * STAGE_P;
        const size_t koff = (size_t)kc * 32;
#pragma unroll
        for (int t = 0; t < 8; t++) {
            const int idx = tid + t * 256;
            const int part = idx >> 10;          // 0=A(Wv), 1=B(xT)
            const int a = idx & 1023;
            const int row = a >> 3, seg = a & 7;
            const __nv_bfloat16* src;
            if (part == 0)
                src = (seg < 4 ? Whi : Wlo) + (size_t)(c0 + row) * C_ + koff + (seg & 3) * 8;
            else
                src = (seg < 4 ? Xhi : Xlo) + (size_t)(n0 + row) * C_ + koff + (seg & 3) * 8;
            cp16(sbase + st + (uint32_t)part * 16384u + swz(row, seg * 16), src);
        }
        asm volatile("cp.async.commit_group;" ::: "memory");
    };

    load_chunk(0);

    for (int kc = 0; kc < C_ / 32; kc++) {
        asm volatile("cp.async.wait_group 0;" ::: "memory");
        __syncthreads();
        if (kc + 1 < C_ / 32) load_chunk(kc + 1);

        const uint32_t st = (uint32_t)(kc & 1) * STAGE_P;
        const uint32_t Ab = sbase + st, Bb = Ab + 16384;

#pragma unroll
        for (int ks = 0; ks < 2; ks++) {
            const uint32_t kbHi = (uint32_t)(ks * 32);
            const uint32_t kbLo = 64u + kbHi;

            uint32_t ah[4][4], al[4][4], bh[2][4], bl[2][4];
#pragma unroll
            for (int i = 0; i < 4; i++) {
                const uint32_t row = (uint32_t)(wm + i * 16) + lrow;
                ldsm4(ah[i], Ab + row * 128u + ((kbHi + lcol) ^ lswz));
                ldsm4(al[i], Ab + row * 128u + ((kbLo + lcol) ^ lswz));
            }
#pragma unroll
            for (int j = 0; j < 2; j++) {
                const uint32_t row = (uint32_t)(wn + j * 16) + lrow;
                ldsm4(bh[j], Bb + row * 128u + ((kbHi + lcol) ^ lswz));
                ldsm4(bl[j], Bb + row * 128u + ((kbLo + lcol) ^ lswz));
            }
#pragma unroll
            for (int i = 0; i < 4; i++)
#pragma unroll
                for (int j = 0; j < 4; j++) {
                    const int t2 = j >> 1, p2 = j & 1;
                    mma_bf16(acc[i][j], ah[i], bh[t2][p2], bh[t2][2 + p2]);
                    mma_bf16(acc[i][j], al[i], bh[t2][p2], bh[t2][2 + p2]);
                    mma_bf16(acc[i][j], ah[i], bl[t2][p2], bl[t2][2 + p2]);
                }
        }
        __syncthreads();
    }

    // Epilogue: c-major rows in smem (n contiguous), add bias, emit fp16.
    float* sOut = reinterpret_cast<float*>(dynsmem);
#pragma unroll
    for (int i = 0; i < 4; i++) {
        const int ct = wm + i * 16 + (lane >> 2);
#pragma unroll
        for (int j = 0; j < 4; j++) {
            const int nt = wn + j * 8 + (lane & 3) * 2;
            sOut[ct * EPI_P + nt]           = acc[i][j][0];
            sOut[ct * EPI_P + nt + 1]       = acc[i][j][1];
            sOut[(ct + 8) * EPI_P + nt]     = acc[i][j][2];
            sOut[(ct + 8) * EPI_P + nt + 1] = acc[i][j][3];
        }
    }
    __syncthreads();

    const int row = tid >> 1;             // c within tile
    const int col0 = (tid & 1) * 64;      // n offset
    const float bv = bias[c0 + row];
    const float* srow = sOut + row * EPI_P + col0;
    __half* dst = vf16 + ((size_t)b * C_ + c0 + row) * N_ + n0 + col0;
#pragma unroll
    for (int v = 0; v < 16; v++) {
        float4 f = *reinterpret_cast<const float4*>(srow + v * 4);
        __half2 h01 = __floats2half2_rn(f.x + bv, f.y + bv);
        __half2 h23 = __floats2half2_rn(f.z + bv, f.w + bv);
        uint2 u;
        u.x = *reinterpret_cast<uint32_t*>(&h01);
        u.y = *reinterpret_cast<uint32_t*>(&h23);
        *reinterpret_cast<uint2*>(dst + v * 4) = u;
    }
}

// ---------------------------------------------------------------------------
// Energy (HMMA, single merged pass): per-batch instance.
// E stores use DEFAULT policy (softmax re-reads within the L2 window).
// ---------------------------------------------------------------------------
__global__ void __launch_bounds__(256)
energy_hmma_kernel(float* __restrict__ attn, int b) {
    extern __shared__ char dynsmem[];
    const uint32_t sbase = smem_u32(dynsmem);

    const int tid  = threadIdx.x;
    const int wid  = tid >> 5;
    const int lane = tid & 31;

    const int n0 = blockIdx.x * 128;
    const int m0 = blockIdx.y * 128;

    const __nv_bfloat16* Qhi = g_qhi + (size_t)b * N_ * D_;
    const __nv_bfloat16* Qlo = g_qlo + (size_t)b * N_ * D_;
    const __nv_bfloat16* Khi = g_khi + (size_t)b * N_ * D_;
    const __nv_bfloat16* Klo = g_klo + (size_t)b * N_ * D_;

    const int wm = (wid >> 2) * 64;
    const int wn = (wid & 3) * 32;

    const uint32_t lrow = lane & 15;
    const uint32_t lswz = (lane & 7) << 4;
    const uint32_t lcol = (lane >> 4) << 4;

    // Load all four 16KB tiles: Qhi@0, Khi@16K, Qlo@32K, Klo@48K.
#pragma unroll
    for (int t = 0; t < 4; t++) {
        const int idx = tid + t * 256;
        const int row = idx >> 3, seg = idx & 7;
        cp16(sbase + swz(row, seg * 16), Qhi + (size_t)(m0 + row) * D_ + seg * 8);
        cp16(sbase + 16384 + swz(row, seg * 16), Khi + (size_t)(n0 + row) * D_ + seg * 8);
        cp16(sbase + 32768 + swz(row, seg * 16), Qlo + (size_t)(m0 + row) * D_ + seg * 8);
        cp16(sbase + 49152 + swz(row, seg * 16), Klo + (size_t)(n0 + row) * D_ + seg * 8);
    }
    asm volatile("cp.async.commit_group;" ::: "memory");

    float acc[4][4][4] = {};

    asm volatile("cp.async.wait_group 0;" ::: "memory");
    __syncthreads();

#pragma unroll
    for (int ks = 0; ks < 4; ks++) {
        const uint32_t kb = (uint32_t)(ks * 32);
        uint32_t ah[4][4], al[4][4], bh[2][4], bl[2][4];
#pragma unroll
        for (int i = 0; i < 4; i++) {
            const uint32_t row = (uint32_t)(wm + i * 16) + lrow;
            ldsm4(ah[i], sbase + row * 128u + ((kb + lcol) ^ lswz));
            ldsm4(al[i], sbase + 32768 + row * 128u + ((kb + lcol) ^ lswz));
        }
#pragma unroll
        for (int j = 0; j < 2; j++) {
            const uint32_t row = (uint32_t)(wn + j * 16) + lrow;
            ldsm4(bh[j], sbase + 16384 + row * 128u + ((kb + lcol) ^ lswz));
            ldsm4(bl[j], sbase + 49152 + row * 128u + ((kb + lcol) ^ lswz));
        }
#pragma unroll
        for (int i = 0; i < 4; i++)
#pragma unroll
            for (int j = 0; j < 4; j++) {
                const int t2 = j >> 1, p2 = j & 1;
                mma_bf16(acc[i][j], ah[i], bh[t2][p2], bh[t2][2 + p2]);
                mma_bf16(acc[i][j], al[i], bh[t2][p2], bh[t2][2 + p2]);
                mma_bf16(acc[i][j], ah[i], bl[t2][p2], bl[t2][2 + p2]);
            }
    }

    __syncthreads();
    float* sOut = reinterpret_cast<float*>(dynsmem);
#pragma unroll
    for (int i = 0; i < 4; i++) {
        const int mt = wm + i * 16 + (lane >> 2);
#pragma unroll
        for (int j = 0; j < 4; j++) {
            const int nt = wn + j * 8 + (lane & 3) * 2;
            sOut[mt * EPI_P + nt]           = acc[i][j][0];
            sOut[mt * EPI_P + nt + 1]       = acc[i][j][1];
            sOut[(mt + 8) * EPI_P + nt]     = acc[i][j][2];
            sOut[(mt + 8) * EPI_P + nt + 1] = acc[i][j][3];
        }
    }
    __syncthreads();

    float* eb = attn + (size_t)b * N_ * N_;
    const int row = tid >> 1;
    const int col0 = (tid & 1) * 64;
    const float* srow = sOut + row * EPI_P + col0;
    float* grow = eb + (size_t)(m0 + row) * N_ + n0 + col0;
#pragma unroll
    for (int v = 0; v < 16; v++)
        *reinterpret_cast<float4*>(grow + v * 4) =
            *reinterpret_cast<const float4*>(srow + v * 4);
}

// ---------------------------------------------------------------------------
// Row softmax in place (per-batch), no max subtraction (logits << 88).
// E load default (L2-hot from energy); attn fp32 store .cs (never re-read).
// ---------------------------------------------------------------------------
__global__ void softmax_kernel(float* __restrict__ attn,
                               __half* __restrict__ af16, int b) {
    const size_t row = (size_t)b * N_ + blockIdx.x;
    float* p = attn + row * N_;
    const int tid = threadIdx.x;

    float4 v[4];
    float s = 0.f;
#pragma unroll
    for (int i = 0; i < 4; i++) {
        v[i] = *reinterpret_cast<const float4*>(p + tid * 4 + i * 1024);
        v[i].x = __expf(v[i].x); v[i].y = __expf(v[i].y);
        v[i].z = __expf(v[i].z); v[i].w = __expf(v[i].w);
        s += (v[i].x + v[i].y) + (v[i].z + v[i].w);
    }
    __shared__ float red[8];
#pragma unroll
    for (int o = 16; o; o >>= 1) s += __shfl_xor_sync(0xffffffffu, s, o);
    if ((tid & 31) == 0) red[tid >> 5] = s;
    __syncthreads();
    s = 0.f;
#pragma unroll
    for (int i = 0; i < 8; i++) s += red[i];
    const float inv = 1.0f / s;

    __half* ph = af16 + row * N_;
#pragma unroll
    for (int i = 0; i < 4; i++) {
        float4 r;
        r.x = v[i].x * inv; r.y = v[i].y * inv; r.z = v[i].z * inv; r.w = v[i].w * inv;
        st_cs_f4(p + tid * 4 + i * 1024, r);

        __half2 h01 = __floats2half2_rn(r.x, r.y);
        __half2 h23 = __floats2half2_rn(r.z, r.w);
        uint2 hh;
        hh.x = *reinterpret_cast<uint32_t*>(&h01);
        hh.y = *reinterpret_cast<uint32_t*>(&h23);
        *reinterpret_cast<uint2*>(ph + tid * 4 + i * 1024) = hh;
    }
}

// ---------------------------------------------------------------------------
// out-GEMM (per-batch): HMMA fp16, CTA 128m x 64c, 2-stage ring, 3 CTAs/SM.
// ---------------------------------------------------------------------------
__global__ void __launch_bounds__(256, 3)
out_gemm_kernel(const float* __restrict__ x,
                const float* __restrict__ gamma,
                float* __restrict__ out, int b) {
    extern __shared__ char dynsmem[];
    const uint32_t sbase = smem_u32(dynsmem);

    const int tid  = threadIdx.x;
    const int wid  = tid >> 5;
    const int lane = tid & 31;

    const int c0 = blockIdx.x * 64;    // c fastest: 8 siblings share A tile in L2
    const int m0 = blockIdx.y * 128;

    const __half* A = g_af16 + (size_t)b * N_ * N_;
    const __half* V = g_vf16 + (size_t)b * C_ * N_;

    const int wm = (wid >> 2) * 64;    // m offset of warp
    const int wc = (wid & 3) * 16;     // c offset of warp

    const uint32_t lrow = lane & 15;
    const uint32_t lswz = (lane & 7) << 4;
    const uint32_t lcol = (lane >> 4) << 4;

    float acc[4][2][4] = {};   // [m16][c8][reg]

    auto load_chunk = [&](int kc) {
        const uint32_t st = (uint32_t)(kc & 1) * STAGE_O;
        const size_t koff = (size_t)kc * KC_O;
#pragma unroll
        for (int t = 0; t < 6; t++) {
            const int idx = tid + t * 256;
            if (idx < 1024) {
                const int row = idx >> 3, seg = idx & 7;
                cp16(sbase + st + swz(row, seg * 16),
                     A + (size_t)(m0 + row) * N_ + koff + seg * 8);
            } else {
                const int i2 = idx - 1024;
                const int row = i2 >> 3, seg = i2 & 7;
                cp16(sbase + st + 16384u + swz(row, seg * 16),
                     V + (size_t)(c0 + row) * N_ + koff + seg * 8);
            }
        }
        asm volatile("cp.async.commit_group;" ::: "memory");
    };

    load_chunk(0);

    for (int kc = 0; kc < NCHUNK_O; kc++) {
        asm volatile("cp.async.wait_group 0;" ::: "memory");
        __syncthreads();
        if (kc + 1 < NCHUNK_O) load_chunk(kc + 1);

        const uint32_t st = (uint32_t)(kc & 1) * STAGE_O;
        const uint32_t Ab = sbase + st, Vb = Ab + 16384;

#pragma unroll
        for (int ks = 0; ks < 4; ks++) {
            const uint32_t kb = (uint32_t)(ks * 32);
            uint32_t a[4][4], bm[4];
#pragma unroll
            for (int i = 0; i < 4; i++) {
                const uint32_t row = (uint32_t)(wm + i * 16) + lrow;
                ldsm4(a[i], Ab + row * 128u + ((kb + lcol) ^ lswz));
            }
            {
                const uint32_t row = (uint32_t)wc + lrow;
                ldsm4(bm, Vb + row * 128u + ((kb + lcol) ^ lswz));
            }
#pragma unroll
            for (int i = 0; i < 4; i++)
#pragma unroll
                for (int p2 = 0; p2 < 2; p2++)
                    mma_f16(acc[i][p2], a[i], bm[p2], bm[2 + p2]);
        }
    }
    __syncthreads();

    // ---- epilogue: full 64c x 128m transpose via smem ----
    float* sOut = reinterpret_cast<float*>(dynsmem);
#pragma unroll
    for (int i = 0; i < 4; i++) {
        const int mt = wm + i * 16 + (lane >> 2);
#pragma unroll
        for (int p2 = 0; p2 < 2; p2++) {
            const int ct = wc + p2 * 8 + (lane & 3) * 2;
            sOut[ct * EPI_P + mt]           = acc[i][p2][0];
            sOut[(ct + 1) * EPI_P + mt]     = acc[i][p2][1];
            sOut[ct * EPI_P + mt + 8]       = acc[i][p2][2];
            sOut[(ct + 1) * EPI_P + mt + 8] = acc[i][p2][3];
        }
    }
    __syncthreads();

    const float g = gamma[0];
    const int ce = tid >> 2;             // 0..63
    const int me = (tid & 3) * 32;       // m offset
    const size_t gb = ((size_t)b * C_ + c0 + ce) * N_ + m0 + me;
    const float* srow = sOut + ce * EPI_P + me;
#pragma unroll
    for (int v = 0; v < 8; v++) {
        const float4 xv = *reinterpret_cast<const float4*>(x + gb + v * 4);
        float4 ov;
        ov.x = g * srow[v * 4 + 0] + xv.x;
        ov.y = g * srow[v * 4 + 1] + xv.y;
        ov.z = g * srow[v * 4 + 2] + xv.z;
        ov.w = g * srow[v * 4 + 3] + xv.w;
        *reinterpret_cast<float4*>(out + gb + v * 4) = ov;
    }
}

// ---------------------------------------------------------------------------
extern "C" void kernel_launch(void* const* d_in, const int* in_sizes, int n_in,
                              void* d_out, int out_size) {
    (void)in_sizes; (void)n_in; (void)out_size;
    const float* x     = (const float*)d_in[0];
    const float* Wq    = (const float*)d_in[1];
    const float* bq    = (const float*)d_in[2];
    const float* Wk    = (const float*)d_in[3];
    const float* bk    = (const float*)d_in[4];
    const float* Wv    = (const float*)d_in[5];
    const float* bv    = (const float*)d_in[6];
    const float* gamma = (const float*)d_in[7];

    float* out  = (float*)d_out;
    float* attn = out + (size_t)B_ * C_ * N_;   // tuple order: (out, attention)

    __nv_bfloat16 *qhi, *qlo, *khi, *klo, *xthi, *xtlo, *wvhi, *wvlo, *wqkhi, *wqklo;
    __half *vf16, *af16;
    cudaGetSymbolAddress((void**)&qhi, g_qhi);
    cudaGetSymbolAddress((void**)&qlo, g_qlo);
    cudaGetSymbolAddress((void**)&khi, g_khi);
    cudaGetSymbolAddress((void**)&klo, g_klo);
    cudaGetSymbolAddress((void**)&xthi, g_xthi);
    cudaGetSymbolAddress((void**)&xtlo, g_xtlo);
    cudaGetSymbolAddress((void**)&wvhi, g_wvhi);
    cudaGetSymbolAddress((void**)&wvlo, g_wvlo);
    cudaGetSymbolAddress((void**)&wqkhi, g_wqkhi);
    cudaGetSymbolAddress((void**)&wqklo, g_wqklo);
    cudaGetSymbolAddress((void**)&vf16, g_vf16);
    cudaGetSymbolAddress((void**)&af16, g_af16);

    cudaFuncSetAttribute(out_gemm_kernel,
                         cudaFuncAttributeMaxDynamicSharedMemorySize, DYN_OUT);
    cudaFuncSetAttribute(energy_hmma_kernel,
                         cudaFuncAttributeMaxDynamicSharedMemorySize, DYN_E);
    cudaFuncSetAttribute(proj_v_hmma_kernel,
                         cudaFuncAttributeMaxDynamicSharedMemorySize, DYN_V);
    cudaFuncSetAttribute(proj_qk_hmma_kernel,
                         cudaFuncAttributeMaxDynamicSharedMemorySize, DYN_QK);

    // ONE extra stream + 6 events (proven-safe resource budget). R13 schedule.
    cudaStream_t s1;
    cudaStreamCreateWithFlags(&s1, cudaStreamNonBlocking);
    cudaEvent_t eFork, eX, eWqk, eV, eQK, eDone;
    cudaEventCreateWithFlags(&eFork, cudaEventDisableTiming);
    cudaEventCreateWithFlags(&eX,    cudaEventDisableTiming);
    cudaEventCreateWithFlags(&eWqk,  cudaEventDisableTiming);
    cudaEventCreateWithFlags(&eV,    cudaEventDisableTiming);
    cudaEventCreateWithFlags(&eQK,   cudaEventDisableTiming);
    cudaEventCreateWithFlags(&eDone, cudaEventDisableTiming);

    dim3 blk(256);

    // fork side stream off the (captured) legacy stream
    cudaEventRecord(eFork, 0);
    cudaStreamWaitEvent(s1, eFork, 0);

    // s1: weight converts (independent of x)
    convert_w_kernel<<<dim3(C_ * C_ / 256), blk, 0, s1>>>(Wv, wvhi, wvlo);
    convert_wqk_kernel<<<dim3(128 * C_ / 256), blk, 0, s1>>>(Wq, Wk, wqkhi, wqklo);
    cudaEventRecord(eWqk, s1);

    // s0: x transpose/split
    convert_x_kernel<<<dim3(N_ / 32, C_ / 32, B_), blk>>>(x, xthi, xtlo);
    cudaEventRecord(eX, 0);

    // s1: proj_v (needs convert_x + convert_w) — overlaps proj_qk/energy(b0)
    cudaStreamWaitEvent(s1, eX, 0);
    proj_v_hmma_kernel<<<dim3(C_ / 128, N_ / 128, B_), blk, DYN_V, s1>>>(bv, vf16);
    cudaEventRecord(eV, s1);

    // s0: proj_qk (needs convert_x + convert_wqk)
    cudaStreamWaitEvent(0, eWqk, 0);
    proj_qk_hmma_kernel<<<dim3(N_ / 128, 1, B_), blk, DYN_QK>>>(bq, bk, qhi, qlo, khi, klo);
    cudaEventRecord(eQK, 0);

    // Two-way batch pipeline: s0 handles b=0,2; s1 handles b=1,3.
    cudaStreamWaitEvent(s1, eQK, 0);
    for (int i = 0; i < 2; i++) {
        const int b0 = 2 * i;      // s0 batches: 0, 2
        const int b1 = 2 * i + 1;  // s1 batches: 1, 3

        energy_hmma_kernel<<<dim3(N_ / 128, N_ / 128, 1), blk, DYN_E, 0>>>(attn, b0);
        energy_hmma_kernel<<<dim3(N_ / 128, N_ / 128, 1), blk, DYN_E, s1>>>(attn, b1);

        softmax_kernel<<<dim3(N_), blk, 0, 0>>>(attn, af16, b0);
        softmax_kernel<<<dim3(N_), blk, 0, s1>>>(attn, af16, b1);

        if (i == 0) cudaStreamWaitEvent(0, eV, 0);   // v ready before first out_gemm
        out_gemm_kernel<<<dim3(C_ / 64, N_ / 128, 1), blk, DYN_OUT, 0>>>(x, gamma, out, b0);
        out_gemm_kernel<<<dim3(C_ / 64, N_ / 128, 1), blk, DYN_OUT, s1>>>(x, gamma, out, b1);
    }

    // join s1 back to the legacy (capture-origin) stream
    cudaEventRecord(eDone, s1);
    cudaStreamWaitEvent(0, eDone, 0);
}